// round 4
// baseline (speedup 1.0000x reference)
#include <cuda_runtime.h>
#include <cstdint>

// Problem constants: B=1024, FANOUTS=[10,25], DIM=256, N_NODES=100000
#define DIM   256
#define D4    64      // DIM / 4
#define HALF  128

typedef unsigned long long u64;

// Scratch (device globals; allocation-free per harness rules)
__device__ float g_n1[10240 * DIM];  // layer0 output on hop-1 nodes
__device__ float g_n0[1024  * DIM];  // layer0 output on hop-0 nodes

// ---- packed f32x2 helpers (ptxas won't auto-fuse FFMA2; must use PTX) ----
__device__ __forceinline__ u64 pack2(float a, float b) {
    u64 r;
    asm("mov.b64 %0, {%1, %2};" : "=l"(r) : "f"(a), "f"(b));
    return r;
}
__device__ __forceinline__ u64 ffma2(u64 a, u64 b, u64 c) {
    u64 d;
    asm("fma.rn.f32x2 %0, %1, %2, %3;" : "=l"(d) : "l"(a), "l"(b), "l"(c));
    return d;
}

// L2-only (L1-bypassing) float4 load: keep L1 free for W.
__device__ __forceinline__ float4 ldcg4(const float4* p) {
    float4 v;
    asm volatile("ld.global.cg.v4.f32 {%0,%1,%2,%3}, [%4];"
                 : "=f"(v.x), "=f"(v.y), "=f"(v.z), "=f"(v.w) : "l"(p));
    return v;
}

// =============================== layer 0 ====================================
// One fused tile of TM rows (both output halves):
//   Xs[r] = feat[ sidx[row] ]
//   Xn[r] = mean_{j<F} feat[ nidx[row*F+j] ]
//   out[row][0:128]   = relu( Xs[r] @ Ws )
//   out[row][128:256] = relu( Xn[r] @ Wn )
template <int TM, int F, int THREADS>
__device__ __forceinline__ void sage0_tile(
    const float4* __restrict__ feat4,
    const int*    __restrict__ sidx,
    const int*    __restrict__ nidx,
    const float*  __restrict__ Ws,   // [256,128] row-major
    const float*  __restrict__ Wn,
    float*        __restrict__ out,  // [nrows,256]
    int m0,
    float4* Xs4, float4* Xn4)
{
    const int tid = threadIdx.x;
    constexpr int ITEMS = TM * D4;

    #pragma unroll
    for (int it = 0; it < ITEMS / THREADS; ++it) {
        const int i = it * THREADS + tid;
        const int r   = i >> 6;
        const int q   = i & 63;
        const int row = m0 + r;

        const int gs = __ldg(sidx + row);
        Xs4[i] = ldcg4(feat4 + (size_t)gs * D4 + q);

        float4 a = make_float4(0.f, 0.f, 0.f, 0.f);
        const size_t nb = (size_t)row * F;
        #pragma unroll
        for (int j = 0; j < F; ++j) {
            const int g = __ldg(nidx + nb + j);
            const float4 v = ldcg4(feat4 + (size_t)g * D4 + q);
            a.x += v.x; a.y += v.y; a.z += v.z; a.w += v.w;
        }
        const float inv = 1.0f / (float)F;
        a.x *= inv; a.y *= inv; a.z *= inv; a.w *= inv;
        Xn4[i] = a;
    }
    __syncthreads();

    // GEMM: thread -> (output column c in [0,256), row-group)
    constexpr int RQ  = THREADS / 256;
    constexpr int RPT = TM / RQ;
    const int c  = tid & 255;
    const int r0 = (tid >> 8) * RPT;
    const bool self_half = (c < HALF);   // warp-uniform
    const float* __restrict__ X  =
        reinterpret_cast<const float*>(self_half ? Xs4 : Xn4);
    const float* __restrict__ Wc = (self_half ? Ws : Wn) + (c & (HALF - 1));

    u64 acc[RPT];
    #pragma unroll
    for (int r = 0; r < RPT; ++r) acc[r] = 0ull;

    #pragma unroll 4
    for (int k0 = 0; k0 < DIM; k0 += 4) {
        const u64 w01 = pack2(__ldg(Wc + (k0 + 0) * HALF), __ldg(Wc + (k0 + 1) * HALF));
        const u64 w23 = pack2(__ldg(Wc + (k0 + 2) * HALF), __ldg(Wc + (k0 + 3) * HALF));
        #pragma unroll
        for (int r = 0; r < RPT; ++r) {
            const ulonglong2 xv =
                *reinterpret_cast<const ulonglong2*>(&X[(r0 + r) * DIM + k0]);
            acc[r] = ffma2(xv.x, w01, acc[r]);
            acc[r] = ffma2(xv.y, w23, acc[r]);
        }
    }

    #pragma unroll
    for (int r = 0; r < RPT; ++r) {
        const float lo = __uint_as_float((unsigned)(acc[r] & 0xffffffffull));
        const float hi = __uint_as_float((unsigned)(acc[r] >> 32));
        out[(size_t)(m0 + r0 + r) * DIM + c] = fmaxf(lo + hi, 0.0f);
    }
}

extern __shared__ float4 smem_dyn[];

// blocks [0,320): n1 (10240 rows, F=25); [320,352): n0 (1024 rows, F=10).
__global__ void __launch_bounds__(1024, 2)
sage_layer0_kernel(const float4* __restrict__ feat4,
                   const int* __restrict__ sn0,
                   const int* __restrict__ sn1,
                   const int* __restrict__ sn2,
                   const float* __restrict__ W0s,
                   const float* __restrict__ W0n,
                   float* __restrict__ n1,
                   float* __restrict__ n0)
{
    float4* Xs4 = smem_dyn;
    float4* Xn4 = smem_dyn + 32 * D4;
    if (blockIdx.x < 320) {
        sage0_tile<32, 25, 1024>(feat4, sn1, sn2, W0s, W0n, n1,
                                 blockIdx.x * 32, Xs4, Xn4);
    } else {
        sage0_tile<32, 10, 1024>(feat4, sn0, sn1, W0s, W0n, n0,
                                 (blockIdx.x - 320) * 32, Xs4, Xn4);
    }
}

// =============================== layer 1 ====================================
// Column-split: each CTA computes ONE 128-column half for a TM-row tile.
// blocks [0,256): self half (X = n0 rows, W1s, cols [0,128))
// blocks [256,512): neigh half (X = mean10 of n1 rows, W1n, cols [128,256))
// 256 threads/CTA, TM=4.
template <int TM, int F>
__device__ __forceinline__ void sage1_tile(
    const float4* __restrict__ src4,   // n0 (F=1) or n1 (F=10), contiguous rows
    const float*  __restrict__ W,      // [256,128]
    float*        __restrict__ out,    // [1024,256]
    int m0, int col_off, float4* X4)
{
    const int tid = threadIdx.x;   // 256
    constexpr int ITEMS = TM * D4; // 256

    {
        const int i = tid;
        const int r = i >> 6;
        const int q = i & 63;
        const size_t nb = (size_t)(m0 + r) * F;
        float4 a = make_float4(0.f, 0.f, 0.f, 0.f);
        #pragma unroll
        for (int j = 0; j < F; ++j) {
            const float4 v = ldcg4(src4 + (nb + j) * D4 + q);
            a.x += v.x; a.y += v.y; a.z += v.z; a.w += v.w;
        }
        const float inv = 1.0f / (float)F;
        a.x *= inv; a.y *= inv; a.z *= inv; a.w *= inv;
        X4[i] = a;
    }
    __syncthreads();

    const float* X = reinterpret_cast<const float*>(X4);
    constexpr int RPT = TM / 2;
    const int c  = tid & (HALF - 1);
    const int r0 = (tid >> 7) * RPT;
    const float* __restrict__ Wc = W + c;

    u64 acc[RPT];
    #pragma unroll
    for (int r = 0; r < RPT; ++r) acc[r] = 0ull;

    #pragma unroll 4
    for (int k0 = 0; k0 < DIM; k0 += 4) {
        const u64 w01 = pack2(__ldg(Wc + (k0 + 0) * HALF), __ldg(Wc + (k0 + 1) * HALF));
        const u64 w23 = pack2(__ldg(Wc + (k0 + 2) * HALF), __ldg(Wc + (k0 + 3) * HALF));
        #pragma unroll
        for (int r = 0; r < RPT; ++r) {
            const ulonglong2 xv =
                *reinterpret_cast<const ulonglong2*>(&X[(r0 + r) * DIM + k0]);
            acc[r] = ffma2(xv.x, w01, acc[r]);
            acc[r] = ffma2(xv.y, w23, acc[r]);
        }
    }

    #pragma unroll
    for (int r = 0; r < RPT; ++r) {
        const float lo = __uint_as_float((unsigned)(acc[r] & 0xffffffffull));
        const float hi = __uint_as_float((unsigned)(acc[r] >> 32));
        out[(size_t)(m0 + r0 + r) * DIM + col_off + c] = lo + hi;
    }
}

__global__ void __launch_bounds__(256)
sage_layer1_kernel(const float4* __restrict__ n0_4,
                   const float4* __restrict__ n1_4,
                   const float* __restrict__ W1s,
                   const float* __restrict__ W1n,
                   float* __restrict__ out)
{
    __shared__ float4 X4[4 * D4];
    if (blockIdx.x < 256) {
        sage1_tile<4, 1>(n0_4, W1s, out, blockIdx.x * 4, 0, X4);
    } else {
        sage1_tile<4, 10>(n1_4, W1n, out, (blockIdx.x - 256) * 4, HALF, X4);
    }
}

// =============================================================================
extern "C" void kernel_launch(void* const* d_in, const int* in_sizes, int n_in,
                              void* d_out, int out_size)
{
    const float4* feat4 = (const float4*)d_in[0];
    const int*    sn0   = (const int*)  d_in[1];
    const int*    sn1   = (const int*)  d_in[2];
    const int*    sn2   = (const int*)  d_in[3];
    const float*  W0s   = (const float*)d_in[4];
    const float*  W0n   = (const float*)d_in[5];
    const float*  W1s   = (const float*)d_in[6];
    const float*  W1n   = (const float*)d_in[7];
    float*        out   = (float*)      d_out;

    float* n1 = nullptr;
    float* n0 = nullptr;
    cudaGetSymbolAddress((void**)&n1, g_n1);
    cudaGetSymbolAddress((void**)&n0, g_n0);

    static bool attr_set = false;
    if (!attr_set) {
        cudaFuncSetAttribute(sage_layer0_kernel,
                             cudaFuncAttributeMaxDynamicSharedMemorySize,
                             64 * 1024);
        attr_set = true;
    }

    sage_layer0_kernel<<<352, 1024, 64 * 1024>>>(
        feat4, sn0, sn1, sn2, W0s, W0n, n1, n0);
    sage_layer1_kernel<<<512, 256>>>(
        (const float4*)n0, (const float4*)n1, W1s, W1n, out);
}

// round 5
// speedup vs baseline: 1.1230x; 1.1230x over previous
#include <cuda_runtime.h>
#include <cstdint>

// Problem constants: B=1024, FANOUTS=[10,25], DIM=256, N_NODES=100000
#define DIM   256
#define D4    64      // DIM / 4
#define HALF  128

typedef unsigned long long u64;

// Scratch (device globals; allocation-free per harness rules)
__device__ float g_n1[10240 * DIM];  // layer0 output on hop-1 nodes
__device__ float g_n0[1024  * DIM];  // layer0 output on hop-0 nodes

// ---- packed f32x2 helpers (ptxas won't auto-fuse FFMA2; must use PTX) ----
__device__ __forceinline__ u64 pack2(float a, float b) {
    u64 r;
    asm("mov.b64 %0, {%1, %2};" : "=l"(r) : "f"(a), "f"(b));
    return r;
}
__device__ __forceinline__ u64 ffma2(u64 a, u64 b, u64 c) {
    u64 d;
    asm("fma.rn.f32x2 %0, %1, %2, %3;" : "=l"(d) : "l"(a), "l"(b), "l"(c));
    return d;
}

// =============================== layer 0 ====================================
// One fused tile of TM rows (both output halves):
//   Xs[r] = feat[ sidx[row] ]
//   Xn[r] = mean_{j<F} feat[ nidx[row*F+j] ]
//   out[row][0:128]   = relu( Xs[r] @ Ws )
//   out[row][128:256] = relu( Xn[r] @ Wn )
template <int TM, int F, int THREADS>
__device__ __forceinline__ void sage0_tile(
    const float4* __restrict__ feat4,
    const int*    __restrict__ sidx,
    const int*    __restrict__ nidx,
    const float*  __restrict__ Ws,   // [256,128] row-major
    const float*  __restrict__ Wn,
    float*        __restrict__ out,  // [nrows,256]
    int m0,
    float4* Xs4, float4* Xn4)
{
    const int tid = threadIdx.x;
    constexpr int ITEMS = TM * D4;

    // ---- gather + mean: one (row, float4-slot) per thread per step.
    // __ldcg intrinsic (NOT volatile asm): ptxas may batch the F loads.
    #pragma unroll
    for (int it = 0; it < ITEMS / THREADS; ++it) {
        const int i = it * THREADS + tid;
        const int r   = i >> 6;
        const int q   = i & 63;
        const int row = m0 + r;

        const int gs = __ldg(sidx + row);
        Xs4[i] = __ldcg(feat4 + (size_t)gs * D4 + q);

        float4 a0 = make_float4(0.f, 0.f, 0.f, 0.f);
        float4 a1 = make_float4(0.f, 0.f, 0.f, 0.f);
        const size_t nb = (size_t)row * F;
        #pragma unroll
        for (int j = 0; j < F; j += 2) {
            const int g0 = __ldg(nidx + nb + j);
            const float4 v0 = __ldcg(feat4 + (size_t)g0 * D4 + q);
            a0.x += v0.x; a0.y += v0.y; a0.z += v0.z; a0.w += v0.w;
            if (j + 1 < F) {
                const int g1 = __ldg(nidx + nb + j + 1);
                const float4 v1 = __ldcg(feat4 + (size_t)g1 * D4 + q);
                a1.x += v1.x; a1.y += v1.y; a1.z += v1.z; a1.w += v1.w;
            }
        }
        const float inv = 1.0f / (float)F;
        a0.x = (a0.x + a1.x) * inv; a0.y = (a0.y + a1.y) * inv;
        a0.z = (a0.z + a1.z) * inv; a0.w = (a0.w + a1.w) * inv;
        Xn4[i] = a0;
    }
    __syncthreads();

    // ---- GEMM: thread -> (output column c in [0,256), row-group) ----
    constexpr int RQ  = THREADS / 256;
    constexpr int RPT = TM / RQ;
    const int c  = tid & 255;
    const int r0 = (tid >> 8) * RPT;
    const bool self_half = (c < HALF);   // warp-uniform
    const float* __restrict__ X  =
        reinterpret_cast<const float*>(self_half ? Xs4 : Xn4);
    const float* __restrict__ Wc = (self_half ? Ws : Wn) + (c & (HALF - 1));

    u64 acc[RPT];
    #pragma unroll
    for (int r = 0; r < RPT; ++r) acc[r] = 0ull;

    #pragma unroll 4
    for (int k0 = 0; k0 < DIM; k0 += 4) {
        const u64 w01 = pack2(__ldg(Wc + (k0 + 0) * HALF), __ldg(Wc + (k0 + 1) * HALF));
        const u64 w23 = pack2(__ldg(Wc + (k0 + 2) * HALF), __ldg(Wc + (k0 + 3) * HALF));
        #pragma unroll
        for (int r = 0; r < RPT; ++r) {
            // warp-uniform smem address -> broadcast, conflict-free
            const ulonglong2 xv =
                *reinterpret_cast<const ulonglong2*>(&X[(r0 + r) * DIM + k0]);
            acc[r] = ffma2(xv.x, w01, acc[r]);
            acc[r] = ffma2(xv.y, w23, acc[r]);
        }
    }

    #pragma unroll
    for (int r = 0; r < RPT; ++r) {
        const float lo = __uint_as_float((unsigned)(acc[r] & 0xffffffffull));
        const float hi = __uint_as_float((unsigned)(acc[r] >> 32));
        out[(size_t)(m0 + r0 + r) * DIM + c] = fmaxf(lo + hi, 0.0f);
    }
}

// blocks [0,640): n1 (10240 rows, F=25); [640,704): n0 (1024 rows, F=10).
// 512 threads, TM=16, 32KB static smem -> 3 CTAs/SM (phase overlap).
__global__ void __launch_bounds__(512, 3)
sage_layer0_kernel(const float4* __restrict__ feat4,
                   const int* __restrict__ sn0,
                   const int* __restrict__ sn1,
                   const int* __restrict__ sn2,
                   const float* __restrict__ W0s,
                   const float* __restrict__ W0n,
                   float* __restrict__ n1,
                   float* __restrict__ n0)
{
    __shared__ float4 Xs4[16 * D4];
    __shared__ float4 Xn4[16 * D4];
    if (blockIdx.x < 640) {
        sage0_tile<16, 25, 512>(feat4, sn1, sn2, W0s, W0n, n1,
                                blockIdx.x * 16, Xs4, Xn4);
    } else {
        sage0_tile<16, 10, 512>(feat4, sn0, sn1, W0s, W0n, n0,
                                (blockIdx.x - 640) * 16, Xs4, Xn4);
    }
}

// =============================== layer 1 ====================================
// Column-split: each CTA computes ONE 128-column half of a TM-row tile.
// blocks [0,256): self half (X = n0 rows, W1s, cols [0,128))
// blocks [256,512): neigh half (X = mean10 of n1 rows, W1n, cols [128,256))
template <int TM, int F>
__device__ __forceinline__ void sage1_tile(
    const float4* __restrict__ src4,   // n0 (F=1) or n1 (F=10), contiguous rows
    const float*  __restrict__ W,      // [256,128]
    float*        __restrict__ out,    // [1024,256]
    int m0, int col_off, float4* X4)
{
    const int tid = threadIdx.x;   // 256

    {
        const int i = tid;
        const int r = i >> 6;
        const int q = i & 63;
        const size_t nb = (size_t)(m0 + r) * F;
        float4 a0 = make_float4(0.f, 0.f, 0.f, 0.f);
        float4 a1 = make_float4(0.f, 0.f, 0.f, 0.f);
        #pragma unroll
        for (int j = 0; j < F; j += 2) {
            const float4 v0 = __ldcg(src4 + (nb + j) * D4 + q);
            a0.x += v0.x; a0.y += v0.y; a0.z += v0.z; a0.w += v0.w;
            if (j + 1 < F) {
                const float4 v1 = __ldcg(src4 + (nb + j + 1) * D4 + q);
                a1.x += v1.x; a1.y += v1.y; a1.z += v1.z; a1.w += v1.w;
            }
        }
        const float inv = 1.0f / (float)F;
        a0.x = (a0.x + a1.x) * inv; a0.y = (a0.y + a1.y) * inv;
        a0.z = (a0.z + a1.z) * inv; a0.w = (a0.w + a1.w) * inv;
        X4[i] = a0;
    }
    __syncthreads();

    const float* X = reinterpret_cast<const float*>(X4);
    constexpr int RPT = TM / 2;
    const int c  = tid & (HALF - 1);
    const int r0 = (tid >> 7) * RPT;
    const float* __restrict__ Wc = W + c;

    u64 acc[RPT];
    #pragma unroll
    for (int r = 0; r < RPT; ++r) acc[r] = 0ull;

    #pragma unroll 4
    for (int k0 = 0; k0 < DIM; k0 += 4) {
        const u64 w01 = pack2(__ldg(Wc + (k0 + 0) * HALF), __ldg(Wc + (k0 + 1) * HALF));
        const u64 w23 = pack2(__ldg(Wc + (k0 + 2) * HALF), __ldg(Wc + (k0 + 3) * HALF));
        #pragma unroll
        for (int r = 0; r < RPT; ++r) {
            const ulonglong2 xv =
                *reinterpret_cast<const ulonglong2*>(&X[(r0 + r) * DIM + k0]);
            acc[r] = ffma2(xv.x, w01, acc[r]);
            acc[r] = ffma2(xv.y, w23, acc[r]);
        }
    }

    #pragma unroll
    for (int r = 0; r < RPT; ++r) {
        const float lo = __uint_as_float((unsigned)(acc[r] & 0xffffffffull));
        const float hi = __uint_as_float((unsigned)(acc[r] >> 32));
        out[(size_t)(m0 + r0 + r) * DIM + col_off + c] = lo + hi;
    }
}

__global__ void __launch_bounds__(256)
sage_layer1_kernel(const float4* __restrict__ n0_4,
                   const float4* __restrict__ n1_4,
                   const float* __restrict__ W1s,
                   const float* __restrict__ W1n,
                   float* __restrict__ out)
{
    __shared__ float4 X4[4 * D4];
    if (blockIdx.x < 256) {
        sage1_tile<4, 1>(n0_4, W1s, out, blockIdx.x * 4, 0, X4);
    } else {
        sage1_tile<4, 10>(n1_4, W1n, out, (blockIdx.x - 256) * 4, HALF, X4);
    }
}

// =============================================================================
extern "C" void kernel_launch(void* const* d_in, const int* in_sizes, int n_in,
                              void* d_out, int out_size)
{
    const float4* feat4 = (const float4*)d_in[0];
    const int*    sn0   = (const int*)  d_in[1];
    const int*    sn1   = (const int*)  d_in[2];
    const int*    sn2   = (const int*)  d_in[3];
    const float*  W0s   = (const float*)d_in[4];
    const float*  W0n   = (const float*)d_in[5];
    const float*  W1s   = (const float*)d_in[6];
    const float*  W1n   = (const float*)d_in[7];
    float*        out   = (float*)      d_out;

    float* n1 = nullptr;
    float* n0 = nullptr;
    cudaGetSymbolAddress((void**)&n1, g_n1);
    cudaGetSymbolAddress((void**)&n0, g_n0);

    sage_layer0_kernel<<<704, 512>>>(feat4, sn0, sn1, sn2, W0s, W0n, n1, n0);
    sage_layer1_kernel<<<512, 256>>>(
        (const float4*)n0, (const float4*)n1, W1s, W1n, out);
}